// round 2
// baseline (speedup 1.0000x reference)
#include <cuda_runtime.h>
#include <math_constants.h>

#define NN 50000
#define EE 1600000
#define DD 128
#define NEG_SLOPE 0.01f

// Scratch (__device__ globals; no allocation allowed)
__device__ int   g_deg[NN];
__device__ int   g_off[NN + 1];
__device__ int   g_cur[NN];
__device__ int   g_srcperm[EE];
__device__ float g_h_mid[NN * DD];   // layer-0 output
__device__ float g_ssrc[NN];
__device__ float g_sdst[NN];

// ---------------- CSR build (once per launch; src/dst fixed for both layers) --

__global__ void k_zero(int n) {
    int i = blockIdx.x * blockDim.x + threadIdx.x;
    if (i < n) g_deg[i] = 0;
}

__global__ void k_hist(const int* __restrict__ dst, int e) {
    int i = blockIdx.x * blockDim.x + threadIdx.x;
    if (i < e) atomicAdd(&g_deg[dst[i]], 1);
}

// Single-block exclusive scan of g_deg -> g_off / g_cur.
__global__ void k_scan(int n, int e) {
    const int T = 1024;
    int t  = threadIdx.x;
    int ch = (n + T - 1) / T;
    int lo = t * ch;
    int hi = min(lo + ch, n);

    int s = 0;
    for (int i = lo; i < hi; i++) s += g_deg[i];

    __shared__ int sums[T];
    sums[t] = s;
    __syncthreads();
    // Hillis-Steele inclusive scan
    for (int o = 1; o < T; o <<= 1) {
        int v = (t >= o) ? sums[t - o] : 0;
        __syncthreads();
        sums[t] += v;
        __syncthreads();
    }
    int run = sums[t] - s;  // exclusive prefix for this thread's chunk
    for (int i = lo; i < hi; i++) {
        g_off[i] = run;
        g_cur[i] = run;
        run += g_deg[i];
    }
    if (t == T - 1) g_off[n] = run;
}

__global__ void k_scatter(const int* __restrict__ src, const int* __restrict__ dst, int e) {
    int i = blockIdx.x * blockDim.x + threadIdx.x;
    if (i < e) {
        int p = atomicAdd(&g_cur[dst[i]], 1);
        g_srcperm[p] = src[i];
    }
}

// ---------------- Per-layer kernels ------------------------------------------

// warp per node: both attention dots for this layer's weights.
__global__ void k_dots(const float* __restrict__ hp, const float* __restrict__ w, int n) {
    int gid  = blockIdx.x * blockDim.x + threadIdx.x;
    int node = gid >> 5;
    int lane = threadIdx.x & 31;
    if (node >= n) return;

    float4 v  = ((const float4*)hp)[node * 32 + lane];
    float4 ws = ((const float4*)w)[lane];
    float4 wd = ((const float4*)w)[32 + lane];
    float ds = v.x * ws.x + v.y * ws.y + v.z * ws.z + v.w * ws.w;
    float dd = v.x * wd.x + v.y * wd.y + v.z * wd.z + v.w * wd.w;
    #pragma unroll
    for (int o = 16; o; o >>= 1) {
        ds += __shfl_xor_sync(0xffffffffu, ds, o);
        dd += __shfl_xor_sync(0xffffffffu, dd, o);
    }
    if (lane == 0) {
        g_ssrc[node] = ds;
        g_sdst[node] = dd;
    }
}

// warp per node: segment softmax + weighted aggregation, all in registers.
__global__ void k_agg(const float* __restrict__ hp, float* __restrict__ out, int n) {
    int gid  = blockIdx.x * blockDim.x + threadIdx.x;
    int node = gid >> 5;
    int lane = threadIdx.x & 31;
    if (node >= n) return;

    int beg = g_off[node];
    int end = g_off[node + 1];
    float sd = g_sdst[node];

    // pass 1: max over edge scores (lane-parallel across edges)
    float mx = -CUDART_INF_F;
    for (int k = beg + lane; k < end; k += 32) {
        int s   = g_srcperm[k];
        float a = g_ssrc[s] + sd;
        float ev = (a > 0.f) ? a : NEG_SLOPE * a;
        mx = fmaxf(mx, ev);
    }
    #pragma unroll
    for (int o = 16; o; o >>= 1)
        mx = fmaxf(mx, __shfl_xor_sync(0xffffffffu, mx, o));

    // pass 2: exp-sum + gather/accumulate (edge-serial, whole warp per row)
    float4 acc = make_float4(0.f, 0.f, 0.f, 0.f);
    float  sum = 0.f;
    for (int base = beg; base < end; base += 32) {
        int k = base + lane;
        int s = 0;
        float ex = 0.f;
        if (k < end) {
            s = g_srcperm[k];
            float a = g_ssrc[s] + sd;
            float ev = (a > 0.f) ? a : NEG_SLOPE * a;
            ex = __expf(ev - mx);
        }
        sum += ex;
        int cnt = min(32, end - base);
        #pragma unroll 4
        for (int j = 0; j < cnt; j++) {
            int   sj  = __shfl_sync(0xffffffffu, s, j);
            float exj = __shfl_sync(0xffffffffu, ex, j);
            float4 hv = ((const float4*)hp)[sj * 32 + lane];
            acc.x += hv.x * exj;
            acc.y += hv.y * exj;
            acc.z += hv.z * exj;
            acc.w += hv.w * exj;
        }
    }
    #pragma unroll
    for (int o = 16; o; o >>= 1)
        sum += __shfl_xor_sync(0xffffffffu, sum, o);

    float inv = (sum != 0.f) ? 1.f / sum : 0.f;
    acc.x *= inv; acc.y *= inv; acc.z *= inv; acc.w *= inv;
    ((float4*)out)[node * 32 + lane] = acc;
}

// ---------------- Launch ------------------------------------------------------

extern "C" void kernel_launch(void* const* d_in, const int* in_sizes, int n_in,
                              void* d_out, int out_size) {
    const float* h   = (const float*)d_in[0];
    const int*   src = (const int*)d_in[1];
    const int*   dst = (const int*)d_in[2];
    const float* att = (const float*)d_in[3];
    int n = in_sizes[0] / DD;
    int e = in_sizes[1];

    int node_blocks = (n * 32 + 255) / 256;
    int n_blocks    = (n + 255) / 256;
    int e_blocks    = (e + 255) / 256;

    // CSR build (shared by both layers)
    k_zero<<<n_blocks, 256>>>(n);
    k_hist<<<e_blocks, 256>>>(dst, e);
    k_scan<<<1, 1024>>>(n, e);
    k_scatter<<<e_blocks, 256>>>(src, dst, e);

    // layer 0: h -> g_h_mid
    k_dots<<<node_blocks, 256>>>(h, att, n);
    k_agg <<<node_blocks, 256>>>(h, g_h_mid, n);

    // layer 1: g_h_mid -> out
    k_dots<<<node_blocks, 256>>>(g_h_mid, att + 2 * DD, n);
    k_agg <<<node_blocks, 256>>>(g_h_mid, (float*)d_out, n);
}

// round 3
// speedup vs baseline: 10.5581x; 10.5581x over previous
#include <cuda_runtime.h>
#include <math_constants.h>

#define NN 50000
#define EE 1600000
#define DD 128
#define NEG_SLOPE 0.01f

// Scratch (__device__ globals; no allocation allowed)
__device__ float g_h_cur[NN * DD];   // normalized features, gather source
__device__ float g_h_acc[NN * DD];   // weighted-sum accumulator
__device__ float g_ssrc[NN];
__device__ float g_sdst[NN];
__device__ float g_ssum[NN];         // segment sum of exp

// K1: one warp per node. Normalize previous layer accumulator (or copy input),
// compute s_src/s_dst dots for this layer, zero accumulator + ssum.
__global__ void k_prep(const float* __restrict__ h_ext, int use_acc,
                       const float* __restrict__ w_row, int n) {
    int gid  = blockIdx.x * blockDim.x + threadIdx.x;
    int node = gid >> 5;
    int lane = threadIdx.x & 31;
    if (node >= n) return;

    float inv = 1.f;
    const float4* src4;
    if (use_acc) {
        float s = g_ssum[node];
        inv  = (s != 0.f) ? 1.f / s : 0.f;
        src4 = (const float4*)g_h_acc;
    } else {
        src4 = (const float4*)h_ext;
    }
    float4 v = src4[node * 32 + lane];
    v.x *= inv; v.y *= inv; v.z *= inv; v.w *= inv;

    ((float4*)g_h_cur)[node * 32 + lane] = v;
    ((float4*)g_h_acc)[node * 32 + lane] = make_float4(0.f, 0.f, 0.f, 0.f);

    float4 ws = ((const float4*)w_row)[lane];        // w_src chunk
    float4 wd = ((const float4*)w_row)[32 + lane];   // w_dst chunk
    float ds = v.x * ws.x + v.y * ws.y + v.z * ws.z + v.w * ws.w;
    float dd = v.x * wd.x + v.y * wd.y + v.z * wd.z + v.w * wd.w;
    #pragma unroll
    for (int o = 16; o; o >>= 1) {
        ds += __shfl_xor_sync(0xffffffffu, ds, o);
        dd += __shfl_xor_sync(0xffffffffu, dd, o);
    }
    if (lane == 0) {
        g_ssrc[node] = ds;
        g_sdst[node] = dd;
        g_ssum[node] = 0.f;
    }
}

// K2: one warp per edge. No max pass: exp(score) directly (scores bounded,
// softmax is shift-invariant). lane0: score + exp + ssum atomic; then the
// warp gathers the 512B source row and red.global.add.v4 into the dst row.
__global__ void k_edge_agg(const int* __restrict__ src, const int* __restrict__ dst, int e) {
    int gw   = (blockIdx.x * blockDim.x + threadIdx.x) >> 5;
    int lane = threadIdx.x & 31;
    if (gw >= e) return;
    int s = src[gw];
    int d = dst[gw];
    float ex = 0.f;
    if (lane == 0) {
        float a  = g_ssrc[s] + g_sdst[d];
        float ev = (a > 0.f) ? a : NEG_SLOPE * a;
        ex = __expf(ev);
        atomicAdd(&g_ssum[d], ex);
    }
    ex = __shfl_sync(0xffffffffu, ex, 0);

    float4 v = ((const float4*)g_h_cur)[s * 32 + lane];
    float rx = v.x * ex, ry = v.y * ex, rz = v.z * ex, rw = v.w * ex;
    float* p = &g_h_acc[d * DD + lane * 4];
    asm volatile("red.global.add.v4.f32 [%0], {%1,%2,%3,%4};"
                 :: "l"(p), "f"(rx), "f"(ry), "f"(rz), "f"(rw)
                 : "memory");
}

// K3: final normalization into d_out.
__global__ void k_final(float* __restrict__ out, int n) {
    int gid = blockIdx.x * blockDim.x + threadIdx.x;  // over n*32 float4s
    if (gid >= n * 32) return;
    int node = gid >> 5;
    float s   = g_ssum[node];
    float inv = (s != 0.f) ? 1.f / s : 0.f;
    float4 v = ((const float4*)g_h_acc)[gid];
    v.x *= inv; v.y *= inv; v.z *= inv; v.w *= inv;
    ((float4*)out)[gid] = v;
}

extern "C" void kernel_launch(void* const* d_in, const int* in_sizes, int n_in,
                              void* d_out, int out_size) {
    const float* h   = (const float*)d_in[0];
    const int*   src = (const int*)d_in[1];
    const int*   dst = (const int*)d_in[2];
    const float* att = (const float*)d_in[3];
    int n = in_sizes[0] / DD;
    int e = in_sizes[1];

    int prep_blocks = (n * 32 + 255) / 256;
    int agg_blocks  = (int)(((long long)e * 32 + 255) / 256);

    for (int l = 0; l < 2; l++) {
        k_prep<<<prep_blocks, 256>>>(h, l > 0, att + (size_t)l * 2 * DD, n);
        k_edge_agg<<<agg_blocks, 256>>>(src, dst, e);
    }
    k_final<<<prep_blocks, 256>>>((float*)d_out, n);
}

// round 4
// speedup vs baseline: 16.0908x; 1.5240x over previous
#include <cuda_runtime.h>
#include <math_constants.h>

#define NN 50000
#define EE 1600000
#define DD 128
#define NEG_SLOPE 0.01f

// Scratch (__device__ globals; no allocation allowed)
__device__ int   g_deg[NN];
__device__ int   g_off[NN + 1];
__device__ int   g_curp[NN];
__device__ int   g_srcperm[EE];   // src id, dst-sorted
__device__ int   g_dsts[EE];      // dst id, dst-sorted
__device__ float g_h_cur[NN * DD];
__device__ float g_h_acc[NN * DD];
__device__ float g_ssrc[NN];
__device__ float g_sdst[NN];
__device__ float g_ssum[NN];

// ---------------- CSR-ish build: dst-sorted edge list (once per launch) -------

__global__ void k_zero(int n) {
    int i = blockIdx.x * blockDim.x + threadIdx.x;
    if (i < n) g_deg[i] = 0;
}

__global__ void k_hist(const int* __restrict__ dst, int e) {
    int i = blockIdx.x * blockDim.x + threadIdx.x;
    if (i < e) atomicAdd(&g_deg[dst[i]], 1);
}

__global__ void k_scan(int n) {
    const int T = 1024;
    int t  = threadIdx.x;
    int ch = (n + T - 1) / T;
    int lo = t * ch;
    int hi = min(lo + ch, n);

    int s = 0;
    for (int i = lo; i < hi; i++) s += g_deg[i];

    __shared__ int sums[T];
    sums[t] = s;
    __syncthreads();
    for (int o = 1; o < T; o <<= 1) {
        int v = (t >= o) ? sums[t - o] : 0;
        __syncthreads();
        sums[t] += v;
        __syncthreads();
    }
    int run = sums[t] - s;
    for (int i = lo; i < hi; i++) {
        g_off[i]  = run;
        g_curp[i] = run;
        run += g_deg[i];
    }
    if (t == T - 1) g_off[n] = run;
}

__global__ void k_scatter(const int* __restrict__ src, const int* __restrict__ dst, int e) {
    int i = blockIdx.x * blockDim.x + threadIdx.x;
    if (i < e) {
        int d = dst[i];
        int p = atomicAdd(&g_curp[d], 1);
        g_srcperm[p] = src[i];
        g_dsts[p]    = d;
    }
}

// ---------------- Per-layer kernels ------------------------------------------

// warp per node: normalize previous accumulator (or copy input), compute the
// two attention dots, zero accumulator + ssum.
__global__ void k_prep(const float* __restrict__ h_ext, int use_acc,
                       const float* __restrict__ w_row, int n) {
    int gid  = blockIdx.x * blockDim.x + threadIdx.x;
    int node = gid >> 5;
    int lane = threadIdx.x & 31;
    if (node >= n) return;

    float inv = 1.f;
    const float4* src4;
    if (use_acc) {
        float s = g_ssum[node];
        inv  = (s != 0.f) ? 1.f / s : 0.f;
        src4 = (const float4*)g_h_acc;
    } else {
        src4 = (const float4*)h_ext;
    }
    float4 v = src4[node * 32 + lane];
    v.x *= inv; v.y *= inv; v.z *= inv; v.w *= inv;

    ((float4*)g_h_cur)[node * 32 + lane] = v;
    ((float4*)g_h_acc)[node * 32 + lane] = make_float4(0.f, 0.f, 0.f, 0.f);

    float4 ws = ((const float4*)w_row)[lane];
    float4 wd = ((const float4*)w_row)[32 + lane];
    float ds = v.x * ws.x + v.y * ws.y + v.z * ws.z + v.w * ws.w;
    float dd = v.x * wd.x + v.y * wd.y + v.z * wd.z + v.w * wd.w;
    #pragma unroll
    for (int o = 16; o; o >>= 1) {
        ds += __shfl_xor_sync(0xffffffffu, ds, o);
        dd += __shfl_xor_sync(0xffffffffu, dd, o);
    }
    if (lane == 0) {
        g_ssrc[node] = ds;
        g_sdst[node] = dd;
        g_ssum[node] = 0.f;
    }
}

__device__ __forceinline__ void flush_row(int d, int lane, const float4& acc, float sum) {
    float* p = &g_h_acc[(size_t)d * DD + lane * 4];
    asm volatile("red.global.add.v4.f32 [%0], {%1,%2,%3,%4};"
                 :: "l"(p), "f"(acc.x), "f"(acc.y), "f"(acc.z), "f"(acc.w)
                 : "memory");
    if (lane == 0) atomicAdd(&g_ssum[d], sum);
}

// One warp per 32 dst-sorted edges. All per-edge scalars are warp-uniform
// (broadcast loads, no shfl). Register accumulation across same-dst runs;
// red.global.add.v4 only on dst-change (~2 per chunk at avg degree 32).
// No max-subtraction: scores are bounded, softmax is shift-invariant.
__global__ void k_agg(int e) {
    int warp = (blockIdx.x * blockDim.x + threadIdx.x) >> 5;
    int lane = threadIdx.x & 31;
    int beg  = warp * 32;
    if (beg >= e) return;
    int cnt = min(32, e - beg);

    const float4* hc = (const float4*)g_h_cur;

    float4 acc = make_float4(0.f, 0.f, 0.f, 0.f);
    float  sum = 0.f;
    int dprev = __ldg(&g_dsts[beg]);

    #pragma unroll
    for (int j = 0; j < 32; j++) {
        if (j >= cnt) break;
        int k = beg + j;
        int s = __ldg(&g_srcperm[k]);
        int d = __ldg(&g_dsts[k]);
        if (d != dprev) {
            flush_row(dprev, lane, acc, sum);
            acc = make_float4(0.f, 0.f, 0.f, 0.f);
            sum = 0.f;
            dprev = d;
        }
        float a  = g_ssrc[s] + g_sdst[d];
        float ev = (a > 0.f) ? a : NEG_SLOPE * a;
        float ex = __expf(ev);
        float4 v = hc[(size_t)s * 32 + lane];
        acc.x = fmaf(v.x, ex, acc.x);
        acc.y = fmaf(v.y, ex, acc.y);
        acc.z = fmaf(v.z, ex, acc.z);
        acc.w = fmaf(v.w, ex, acc.w);
        sum  += ex;
    }
    flush_row(dprev, lane, acc, sum);
}

// final normalization into d_out.
__global__ void k_final(float* __restrict__ out, int n) {
    int gid = blockIdx.x * blockDim.x + threadIdx.x;  // over n*32 float4s
    if (gid >= n * 32) return;
    int node = gid >> 5;
    float s   = g_ssum[node];
    float inv = (s != 0.f) ? 1.f / s : 0.f;
    float4 v = ((const float4*)g_h_acc)[gid];
    v.x *= inv; v.y *= inv; v.z *= inv; v.w *= inv;
    ((float4*)out)[gid] = v;
}

// ---------------- Launch ------------------------------------------------------

extern "C" void kernel_launch(void* const* d_in, const int* in_sizes, int n_in,
                              void* d_out, int out_size) {
    const float* h   = (const float*)d_in[0];
    const int*   src = (const int*)d_in[1];
    const int*   dst = (const int*)d_in[2];
    const float* att = (const float*)d_in[3];
    int n = in_sizes[0] / DD;
    int e = in_sizes[1];

    int node_blocks = (n * 32 + 255) / 256;
    int n_blocks    = (n + 255) / 256;
    int e_blocks    = (e + 255) / 256;
    int agg_warps   = (e + 31) / 32;
    int agg_blocks  = (agg_warps * 32 + 255) / 256;

    // Build dst-sorted edge list (shared by both layers)
    k_zero<<<n_blocks, 256>>>(n);
    k_hist<<<e_blocks, 256>>>(dst, e);
    k_scan<<<1, 1024>>>(n);
    k_scatter<<<e_blocks, 256>>>(src, dst, e);

    for (int l = 0; l < 2; l++) {
        k_prep<<<node_blocks, 256>>>(h, l > 0, att + (size_t)l * 2 * DD, n);
        k_agg<<<agg_blocks, 256>>>(e);
    }
    k_final<<<node_blocks, 256>>>((float*)d_out, n);
}

// round 5
// speedup vs baseline: 16.3421x; 1.0156x over previous
#include <cuda_runtime.h>
#include <cuda_fp16.h>
#include <math_constants.h>

#define NN 50000
#define EE 1600000
#define DD 128
#define NEG_SLOPE 0.01f

// Scratch (__device__ globals; no allocation allowed)
__device__ int    g_deg[NN];
__device__ int    g_off[NN + 1];
__device__ int    g_curp[NN];
__device__ int2   g_edge[EE];        // (src, dst), dst-sorted
__device__ __half g_h_curh[NN * DD]; // fp16 gather source (layer-local)
__device__ float  g_h_acc[NN * DD];  // fp32 accumulator
__device__ float  g_ssrc[NN];
__device__ float  g_sdst[NN];
__device__ float  g_ssum[NN];

// ---------------- CSR-ish build: dst-sorted edge list (once per launch) -------

__global__ void k_zero(int n) {
    int i = blockIdx.x * blockDim.x + threadIdx.x;
    if (i < n) g_deg[i] = 0;
}

__global__ void k_hist(const int* __restrict__ dst, int e) {
    int i = blockIdx.x * blockDim.x + threadIdx.x;
    if (i < e) atomicAdd(&g_deg[dst[i]], 1);
}

__global__ void k_scan(int n) {
    const int T = 1024;
    int t  = threadIdx.x;
    int ch = (n + T - 1) / T;
    int lo = t * ch;
    int hi = min(lo + ch, n);

    int s = 0;
    for (int i = lo; i < hi; i++) s += g_deg[i];

    __shared__ int sums[T];
    sums[t] = s;
    __syncthreads();
    for (int o = 1; o < T; o <<= 1) {
        int v = (t >= o) ? sums[t - o] : 0;
        __syncthreads();
        sums[t] += v;
        __syncthreads();
    }
    int run = sums[t] - s;
    for (int i = lo; i < hi; i++) {
        g_off[i]  = run;
        g_curp[i] = run;
        run += g_deg[i];
    }
    if (t == T - 1) g_off[n] = run;
}

__global__ void k_scatter(const int* __restrict__ src, const int* __restrict__ dst, int e) {
    int i = blockIdx.x * blockDim.x + threadIdx.x;
    if (i < e) {
        int d = dst[i];
        int p = atomicAdd(&g_curp[d], 1);
        g_edge[p] = make_int2(src[i], d);
    }
}

// ---------------- Per-layer kernels ------------------------------------------

// warp per node: normalize previous accumulator (or copy input) into fp16
// gather buffer, compute the two attention dots (fp32), zero acc + ssum.
__global__ void k_prep(const float* __restrict__ h_ext, int use_acc,
                       const float* __restrict__ w_row, int n) {
    int gid  = blockIdx.x * blockDim.x + threadIdx.x;
    int node = gid >> 5;
    int lane = threadIdx.x & 31;
    if (node >= n) return;

    float inv = 1.f;
    const float4* src4;
    if (use_acc) {
        float s = g_ssum[node];
        inv  = (s != 0.f) ? 1.f / s : 0.f;
        src4 = (const float4*)g_h_acc;
    } else {
        src4 = (const float4*)h_ext;
    }
    float4 v = src4[node * 32 + lane];
    v.x *= inv; v.y *= inv; v.z *= inv; v.w *= inv;

    // fp16 gather source
    __half2 p01 = __floats2half2_rn(v.x, v.y);
    __half2 p23 = __floats2half2_rn(v.z, v.w);
    uint2 pk;
    pk.x = *(unsigned int*)&p01;
    pk.y = *(unsigned int*)&p23;
    ((uint2*)g_h_curh)[node * 32 + lane] = pk;

    ((float4*)g_h_acc)[node * 32 + lane] = make_float4(0.f, 0.f, 0.f, 0.f);

    float4 ws = ((const float4*)w_row)[lane];
    float4 wd = ((const float4*)w_row)[32 + lane];
    float ds = v.x * ws.x + v.y * ws.y + v.z * ws.z + v.w * ws.w;
    float dd = v.x * wd.x + v.y * wd.y + v.z * wd.z + v.w * wd.w;
    #pragma unroll
    for (int o = 16; o; o >>= 1) {
        ds += __shfl_xor_sync(0xffffffffu, ds, o);
        dd += __shfl_xor_sync(0xffffffffu, dd, o);
    }
    if (lane == 0) {
        g_ssrc[node] = ds;
        g_sdst[node] = dd;
        g_ssum[node] = 0.f;
    }
}

__device__ __forceinline__ void flush_row(int d, int lane, const float4& acc, float sum) {
    float* p = &g_h_acc[(size_t)d * DD + lane * 4];
    asm volatile("red.global.add.v4.f32 [%0], {%1,%2,%3,%4};"
                 :: "l"(p), "f"(acc.x), "f"(acc.y), "f"(acc.z), "f"(acc.w)
                 : "memory");
    if (lane == 0) atomicAdd(&g_ssum[d], sum);
}

// One warp per 32 dst-sorted edges. Per-edge scalars warp-uniform (broadcast
// loads). fp16 gather (256 B/row), fp32 accumulate; RED only on dst change.
// No max-subtraction: scores bounded, softmax shift-invariant.
__global__ void k_agg(int e) {
    int warp = (blockIdx.x * blockDim.x + threadIdx.x) >> 5;
    int lane = threadIdx.x & 31;
    int beg  = warp * 32;
    if (beg >= e) return;
    int cnt = min(32, e - beg);

    const uint2* hc = (const uint2*)g_h_curh;

    float4 acc = make_float4(0.f, 0.f, 0.f, 0.f);
    float  sum = 0.f;
    int dprev = __ldg(&g_edge[beg].y);

    #pragma unroll
    for (int j = 0; j < 32; j++) {
        if (j >= cnt) break;
        int2 ed = __ldg(&g_edge[beg + j]);
        int  s  = ed.x;
        int  d  = ed.y;
        if (d != dprev) {
            flush_row(dprev, lane, acc, sum);
            acc = make_float4(0.f, 0.f, 0.f, 0.f);
            sum = 0.f;
            dprev = d;
        }
        float a  = g_ssrc[s] + g_sdst[d];
        float ev = (a > 0.f) ? a : NEG_SLOPE * a;
        float ex = __expf(ev);

        uint2 pk = hc[(size_t)s * 32 + lane];
        float2 f01 = __half22float2(*(__half2*)&pk.x);
        float2 f23 = __half22float2(*(__half2*)&pk.y);
        acc.x = fmaf(f01.x, ex, acc.x);
        acc.y = fmaf(f01.y, ex, acc.y);
        acc.z = fmaf(f23.x, ex, acc.z);
        acc.w = fmaf(f23.y, ex, acc.w);
        sum  += ex;
    }
    flush_row(dprev, lane, acc, sum);
}

// final normalization into d_out.
__global__ void k_final(float* __restrict__ out, int n) {
    int gid = blockIdx.x * blockDim.x + threadIdx.x;  // over n*32 float4s
    if (gid >= n * 32) return;
    int node = gid >> 5;
    float s   = g_ssum[node];
    float inv = (s != 0.f) ? 1.f / s : 0.f;
    float4 v = ((const float4*)g_h_acc)[gid];
    v.x *= inv; v.y *= inv; v.z *= inv; v.w *= inv;
    ((float4*)out)[gid] = v;
}

// ---------------- Launch ------------------------------------------------------

extern "C" void kernel_launch(void* const* d_in, const int* in_sizes, int n_in,
                              void* d_out, int out_size) {
    const float* h   = (const float*)d_in[0];
    const int*   src = (const int*)d_in[1];
    const int*   dst = (const int*)d_in[2];
    const float* att = (const float*)d_in[3];
    int n = in_sizes[0] / DD;
    int e = in_sizes[1];

    int node_blocks = (n * 32 + 255) / 256;
    int n_blocks    = (n + 255) / 256;
    int e_blocks    = (e + 255) / 256;
    int agg_warps   = (e + 31) / 32;
    int agg_blocks  = (agg_warps * 32 + 255) / 256;

    // Build dst-sorted edge list (shared by both layers)
    k_zero<<<n_blocks, 256>>>(n);
    k_hist<<<e_blocks, 256>>>(dst, e);
    k_scan<<<1, 1024>>>(n);
    k_scatter<<<e_blocks, 256>>>(src, dst, e);

    for (int l = 0; l < 2; l++) {
        k_prep<<<node_blocks, 256>>>(h, l > 0, att + (size_t)l * 2 * DD, n);
        k_agg<<<agg_blocks, 256>>>(e);
    }
    k_final<<<node_blocks, 256>>>((float*)d_out, n);
}

// round 6
// speedup vs baseline: 18.0733x; 1.1059x over previous
#include <cuda_runtime.h>
#include <cuda_fp16.h>
#include <math_constants.h>

#define NN 50000
#define EE 1600000
#define DD 128
#define NEG_SLOPE 0.01f

// Scratch (__device__ globals; no allocation allowed)
__device__ int    g_deg[NN];
__device__ int    g_off[NN + 1];
__device__ int    g_curp[NN];
__device__ int2   g_edge[EE];        // (src, dst), dst-sorted
__device__ int4   g_ew[EE];          // (src, dst, exp-weight bits, unused)
__device__ __half g_h_curh[NN * DD]; // fp16 gather source (layer-local)
__device__ float  g_h_acc[NN * DD];  // fp32 accumulator
__device__ float  g_ssrc[NN];
__device__ float  g_sdst[NN];
__device__ float  g_ssum[NN];

// ---------------- CSR-ish build: dst-sorted edge list (once per launch) -------

__global__ void k_zero(int n) {
    int i = blockIdx.x * blockDim.x + threadIdx.x;
    if (i < n) g_deg[i] = 0;
}

__global__ void k_hist(const int* __restrict__ dst, int e) {
    int i = blockIdx.x * blockDim.x + threadIdx.x;
    if (i < e) atomicAdd(&g_deg[dst[i]], 1);
}

__global__ void k_scan(int n) {
    const int T = 1024;
    int t  = threadIdx.x;
    int ch = (n + T - 1) / T;
    int lo = t * ch;
    int hi = min(lo + ch, n);

    int s = 0;
    for (int i = lo; i < hi; i++) s += g_deg[i];

    __shared__ int sums[T];
    sums[t] = s;
    __syncthreads();
    for (int o = 1; o < T; o <<= 1) {
        int v = (t >= o) ? sums[t - o] : 0;
        __syncthreads();
        sums[t] += v;
        __syncthreads();
    }
    int run = sums[t] - s;
    for (int i = lo; i < hi; i++) {
        g_off[i]  = run;
        g_curp[i] = run;
        run += g_deg[i];
    }
    if (t == T - 1) g_off[n] = run;
}

__global__ void k_scatter(const int* __restrict__ src, const int* __restrict__ dst, int e) {
    int i = blockIdx.x * blockDim.x + threadIdx.x;
    if (i < e) {
        int d = dst[i];
        int p = atomicAdd(&g_curp[d], 1);
        g_edge[p] = make_int2(src[i], d);
    }
}

// ---------------- Per-layer kernels ------------------------------------------

// warp per node: normalize previous accumulator (or copy input) into fp16
// gather buffer, compute the two attention dots (fp32), zero acc + ssum.
__global__ void k_prep(const float* __restrict__ h_ext, int use_acc,
                       const float* __restrict__ w_row, int n) {
    int gid  = blockIdx.x * blockDim.x + threadIdx.x;
    int node = gid >> 5;
    int lane = threadIdx.x & 31;
    if (node >= n) return;

    float inv = 1.f;
    const float4* src4;
    if (use_acc) {
        float s = g_ssum[node];
        inv  = (s != 0.f) ? 1.f / s : 0.f;
        src4 = (const float4*)g_h_acc;
    } else {
        src4 = (const float4*)h_ext;
    }
    float4 v = src4[node * 32 + lane];
    v.x *= inv; v.y *= inv; v.z *= inv; v.w *= inv;

    __half2 p01 = __floats2half2_rn(v.x, v.y);
    __half2 p23 = __floats2half2_rn(v.z, v.w);
    uint2 pk;
    pk.x = *(unsigned int*)&p01;
    pk.y = *(unsigned int*)&p23;
    ((uint2*)g_h_curh)[node * 32 + lane] = pk;

    ((float4*)g_h_acc)[node * 32 + lane] = make_float4(0.f, 0.f, 0.f, 0.f);

    float4 ws = ((const float4*)w_row)[lane];
    float4 wd = ((const float4*)w_row)[32 + lane];
    float ds = v.x * ws.x + v.y * ws.y + v.z * ws.z + v.w * ws.w;
    float dd = v.x * wd.x + v.y * wd.y + v.z * wd.z + v.w * wd.w;
    #pragma unroll
    for (int o = 16; o; o >>= 1) {
        ds += __shfl_xor_sync(0xffffffffu, ds, o);
        dd += __shfl_xor_sync(0xffffffffu, dd, o);
    }
    if (lane == 0) {
        g_ssrc[node] = ds;
        g_sdst[node] = dd;
        g_ssum[node] = 0.f;
    }
}

// lane-parallel per-edge weight: ex = exp(leakyrelu(ssrc[s] + sdst[d])).
// No max-subtraction (scores bounded; softmax shift-invariant).
__global__ void k_w(int e) {
    int i = blockIdx.x * blockDim.x + threadIdx.x;
    if (i >= e) return;
    int2 ed = __ldg(&g_edge[i]);
    float a  = g_ssrc[ed.x] + g_sdst[ed.y];
    float ev = (a > 0.f) ? a : NEG_SLOPE * a;
    float ex = __expf(ev);
    g_ew[i] = make_int4(ed.x, ed.y, __float_as_int(ex), 0);
}

__device__ __forceinline__ void flush_row(int d, int lane, const float4& acc, float sum) {
    float* p = &g_h_acc[(size_t)d * DD + lane * 4];
    asm volatile("red.global.add.v4.f32 [%0], {%1,%2,%3,%4};"
                 :: "l"(p), "f"(acc.x), "f"(acc.y), "f"(acc.z), "f"(acc.w)
                 : "memory");
    if (lane == 0) atomicAdd(&g_ssum[d], sum);
}

// One warp per 32 dst-sorted edges. Loop body: one uniform LDG.128 (edge+weight,
// addresses known at entry -> batchable), one gather LDG.64, 4 FMA, rare flush.
__global__ void k_agg(int e) {
    int warp = (blockIdx.x * blockDim.x + threadIdx.x) >> 5;
    int lane = threadIdx.x & 31;
    int beg  = warp * 32;
    if (beg >= e) return;

    const uint2* hc = (const uint2*)g_h_curh;
    const int4*  ew = g_ew + beg;

    float4 acc = make_float4(0.f, 0.f, 0.f, 0.f);
    float  sum = 0.f;
    int dprev = __ldg(&ew[0].y);

    if (beg + 32 <= e) {
        // full chunk: branch-free trip count, unrollable + pipelinable
        #pragma unroll
        for (int j = 0; j < 32; j++) {
            int4 q = __ldg(&ew[j]);
            if (q.y != dprev) {
                flush_row(dprev, lane, acc, sum);
                acc = make_float4(0.f, 0.f, 0.f, 0.f);
                sum = 0.f;
                dprev = q.y;
            }
            float ex = __int_as_float(q.z);
            uint2 pk = hc[(size_t)q.x * 32 + lane];
            float2 f01 = __half22float2(*(__half2*)&pk.x);
            float2 f23 = __half22float2(*(__half2*)&pk.y);
            acc.x = fmaf(f01.x, ex, acc.x);
            acc.y = fmaf(f01.y, ex, acc.y);
            acc.z = fmaf(f23.x, ex, acc.z);
            acc.w = fmaf(f23.y, ex, acc.w);
            sum  += ex;
        }
    } else {
        int cnt = e - beg;
        for (int j = 0; j < cnt; j++) {
            int4 q = __ldg(&ew[j]);
            if (q.y != dprev) {
                flush_row(dprev, lane, acc, sum);
                acc = make_float4(0.f, 0.f, 0.f, 0.f);
                sum = 0.f;
                dprev = q.y;
            }
            float ex = __int_as_float(q.z);
            uint2 pk = hc[(size_t)q.x * 32 + lane];
            float2 f01 = __half22float2(*(__half2*)&pk.x);
            float2 f23 = __half22float2(*(__half2*)&pk.y);
            acc.x = fmaf(f01.x, ex, acc.x);
            acc.y = fmaf(f01.y, ex, acc.y);
            acc.z = fmaf(f23.x, ex, acc.z);
            acc.w = fmaf(f23.y, ex, acc.w);
            sum  += ex;
        }
    }
    flush_row(dprev, lane, acc, sum);
}

// final normalization into d_out.
__global__ void k_final(float* __restrict__ out, int n) {
    int gid = blockIdx.x * blockDim.x + threadIdx.x;  // over n*32 float4s
    if (gid >= n * 32) return;
    int node = gid >> 5;
    float s   = g_ssum[node];
    float inv = (s != 0.f) ? 1.f / s : 0.f;
    float4 v = ((const float4*)g_h_acc)[gid];
    v.x *= inv; v.y *= inv; v.z *= inv; v.w *= inv;
    ((float4*)out)[gid] = v;
}

// ---------------- Launch ------------------------------------------------------

extern "C" void kernel_launch(void* const* d_in, const int* in_sizes, int n_in,
                              void* d_out, int out_size) {
    const float* h   = (const float*)d_in[0];
    const int*   src = (const int*)d_in[1];
    const int*   dst = (const int*)d_in[2];
    const float* att = (const float*)d_in[3];
    int n = in_sizes[0] / DD;
    int e = in_sizes[1];

    int node_blocks = (n * 32 + 255) / 256;
    int n_blocks    = (n + 255) / 256;
    int e_blocks    = (e + 255) / 256;
    int agg_warps   = (e + 31) / 32;
    int agg_blocks  = (agg_warps * 32 + 255) / 256;

    // Build dst-sorted edge list (shared by both layers)
    k_zero<<<n_blocks, 256>>>(n);
    k_hist<<<e_blocks, 256>>>(dst, e);
    k_scan<<<1, 1024>>>(n);
    k_scatter<<<e_blocks, 256>>>(src, dst, e);

    for (int l = 0; l < 2; l++) {
        k_prep<<<node_blocks, 256>>>(h, l > 0, att + (size_t)l * 2 * DD, n);
        k_w<<<e_blocks, 256>>>(e);
        k_agg<<<agg_blocks, 256>>>(e);
    }
    k_final<<<node_blocks, 256>>>((float*)d_out, n);
}

// round 8
// speedup vs baseline: 21.1680x; 1.1712x over previous
#include <cuda_runtime.h>
#include <cuda_fp16.h>
#include <math_constants.h>

#define NN 50000
#define EE 1600000
#define DD 128
#define NEG_SLOPE 0.01f

// Scratch (__device__ globals; no allocation allowed)
__device__ int   g_deg[NN];
__device__ int   g_off[NN + 1];
__device__ int   g_curp[NN];
__device__ int2  g_ew[EE];          // (.x = src | dst<<16, .y = exp-weight bits), dst-sorted
__device__ uint2 g_hA[NN * 32];     // fp16x4 per lane: layer-0 gather source
__device__ uint2 g_hB[NN * 32];     // fp16x4 per lane: layer-1 gather source (mid)
__device__ float g_ssrc[NN];
__device__ float g_sdst[NN];

// ---------------- build ---------------------------------------------------------

__global__ void k_zero(int n) {
    int i = blockIdx.x * blockDim.x + threadIdx.x;
    if (i < n) g_deg[i] = 0;
}

__global__ void k_hist(const int* __restrict__ dst, int e) {
    int i = blockIdx.x * blockDim.x + threadIdx.x;
    if (i < e) atomicAdd(&g_deg[dst[i]], 1);
}

__global__ void k_scan(int n) {
    const int T = 1024;
    int t  = threadIdx.x;
    int ch = (n + T - 1) / T;
    int lo = t * ch;
    int hi = min(lo + ch, n);

    int s = 0;
    for (int i = lo; i < hi; i++) s += g_deg[i];

    __shared__ int sums[T];
    sums[t] = s;
    __syncthreads();
    for (int o = 1; o < T; o <<= 1) {
        int v = (t >= o) ? sums[t - o] : 0;
        __syncthreads();
        sums[t] += v;
        __syncthreads();
    }
    int run = sums[t] - s;
    for (int i = lo; i < hi; i++) {
        g_off[i]  = run;
        g_curp[i] = run;
        run += g_deg[i];
    }
    if (t == T - 1) g_off[n] = run;
}

// scatter + layer-0 edge weight in one pass (ssrc/sdst already computed by k_prep0).
// No max-subtraction: scores bounded, softmax shift-invariant.
__global__ void k_scatter_ex(const int* __restrict__ src, const int* __restrict__ dst, int e) {
    int i = blockIdx.x * blockDim.x + threadIdx.x;
    if (i >= e) return;
    int s = src[i], d = dst[i];
    float a  = g_ssrc[s] + g_sdst[d];
    float ev = (a > 0.f) ? a : NEG_SLOPE * a;
    float ex = __expf(ev);
    int p = atomicAdd(&g_curp[d], 1);
    g_ew[p] = make_int2((int)((unsigned)s | ((unsigned)d << 16)), __float_as_int(ex));
}

// ---------------- per-layer -----------------------------------------------------

// warp per node: convert external fp32 h into fp16 gather buffer A,
// compute layer-0 attention dots.
__global__ void k_prep0(const float* __restrict__ h_ext, const float* __restrict__ w_row, int n) {
    int gid  = blockIdx.x * blockDim.x + threadIdx.x;
    int node = gid >> 5;
    int lane = threadIdx.x & 31;
    if (node >= n) return;

    float4 v = ((const float4*)h_ext)[node * 32 + lane];
    __half2 p01 = __floats2half2_rn(v.x, v.y);
    __half2 p23 = __floats2half2_rn(v.z, v.w);
    uint2 pk;
    pk.x = *(unsigned int*)&p01;
    pk.y = *(unsigned int*)&p23;
    g_hA[node * 32 + lane] = pk;

    float4 ws = ((const float4*)w_row)[lane];
    float4 wd = ((const float4*)w_row)[32 + lane];
    float ds = v.x * ws.x + v.y * ws.y + v.z * ws.z + v.w * ws.w;
    float dd = v.x * wd.x + v.y * wd.y + v.z * wd.z + v.w * wd.w;
    #pragma unroll
    for (int o = 16; o; o >>= 1) {
        ds += __shfl_xor_sync(0xffffffffu, ds, o);
        dd += __shfl_xor_sync(0xffffffffu, dd, o);
    }
    if (lane == 0) {
        g_ssrc[node] = ds;
        g_sdst[node] = dd;
    }
}

// warp per node: layer-1 attention dots from fp16 mid buffer B.
__global__ void k_dots1(const float* __restrict__ w_row, int n) {
    int gid  = blockIdx.x * blockDim.x + threadIdx.x;
    int node = gid >> 5;
    int lane = threadIdx.x & 31;
    if (node >= n) return;

    uint2 pk = g_hB[node * 32 + lane];
    float2 f01 = __half22float2(*(__half2*)&pk.x);
    float2 f23 = __half22float2(*(__half2*)&pk.y);

    float4 ws = ((const float4*)w_row)[lane];
    float4 wd = ((const float4*)w_row)[32 + lane];
    float ds = f01.x * ws.x + f01.y * ws.y + f23.x * ws.z + f23.y * ws.w;
    float dd = f01.x * wd.x + f01.y * wd.y + f23.x * wd.z + f23.y * wd.w;
    #pragma unroll
    for (int o = 16; o; o >>= 1) {
        ds += __shfl_xor_sync(0xffffffffu, ds, o);
        dd += __shfl_xor_sync(0xffffffffu, dd, o);
    }
    if (lane == 0) {
        g_ssrc[node] = ds;
        g_sdst[node] = dd;
    }
}

// per-edge layer-1 weight refresh (src/dst unpacked from packed word).
__global__ void k_w1(int e) {
    int i = blockIdx.x * blockDim.x + threadIdx.x;
    if (i >= e) return;
    unsigned p = (unsigned)__ldg(&g_ew[i].x);
    int s = (int)(p & 0xFFFFu);
    int d = (int)(p >> 16);
    float a  = g_ssrc[s] + g_sdst[d];
    float ev = (a > 0.f) ? a : NEG_SLOPE * a;
    g_ew[i].y = __float_as_int(__expf(ev));
}

// One warp per node: softmax-weighted aggregation over the node's dst-sorted
// edge run. Loop body: one uniform broadcast LDG.64 (edge record) + one
// coalesced gather LDG.64 + 4 FMA. Register accumulator, normalized direct
// write. No atomics, no RED, no second pass. Buffers selected DEVICE-side
// via template flags (host cannot take the address of __device__ globals).
template <bool SRC_A, bool FP32OUT>
__global__ void k_agg(float* __restrict__ out_f32, int n) {
    int gid  = blockIdx.x * blockDim.x + threadIdx.x;
    int node = gid >> 5;
    int lane = threadIdx.x & 31;
    if (node >= n) return;

    const uint2* __restrict__ hsrc = SRC_A ? g_hA : g_hB;

    int beg = g_off[node];
    int end = g_off[node + 1];

    float4 acc = make_float4(0.f, 0.f, 0.f, 0.f);
    float  sum = 0.f;

    #pragma unroll 4
    for (int k = beg; k < end; k++) {
        int2 q = __ldg(&g_ew[k]);
        int s = (int)((unsigned)q.x & 0xFFFFu);
        float ex = __int_as_float(q.y);
        uint2 pk = __ldg(&hsrc[(size_t)s * 32 + lane]);
        float2 f01 = __half22float2(*(__half2*)&pk.x);
        float2 f23 = __half22float2(*(__half2*)&pk.y);
        acc.x = fmaf(f01.x, ex, acc.x);
        acc.y = fmaf(f01.y, ex, acc.y);
        acc.z = fmaf(f23.x, ex, acc.z);
        acc.w = fmaf(f23.y, ex, acc.w);
        sum  += ex;
    }

    float inv = (sum != 0.f) ? 1.f / sum : 0.f;
    acc.x *= inv; acc.y *= inv; acc.z *= inv; acc.w *= inv;

    if (FP32OUT) {
        ((float4*)out_f32)[node * 32 + lane] = acc;
    } else {
        __half2 p01 = __floats2half2_rn(acc.x, acc.y);
        __half2 p23 = __floats2half2_rn(acc.z, acc.w);
        uint2 pk;
        pk.x = *(unsigned int*)&p01;
        pk.y = *(unsigned int*)&p23;
        g_hB[node * 32 + lane] = pk;
    }
}

// ---------------- launch --------------------------------------------------------

extern "C" void kernel_launch(void* const* d_in, const int* in_sizes, int n_in,
                              void* d_out, int out_size) {
    const float* h   = (const float*)d_in[0];
    const int*   src = (const int*)d_in[1];
    const int*   dst = (const int*)d_in[2];
    const float* att = (const float*)d_in[3];
    int n = in_sizes[0] / DD;
    int e = in_sizes[1];

    int node_blocks = (n * 32 + 255) / 256;
    int n_blocks    = (n + 255) / 256;
    int e_blocks    = (e + 255) / 256;

    // layer-0 scalars + fp16 buffer (independent of build)
    k_prep0<<<node_blocks, 256>>>(h, att, n);

    // build dst-sorted packed edge list, with layer-0 weights fused in
    k_zero<<<n_blocks, 256>>>(n);
    k_hist<<<e_blocks, 256>>>(dst, e);
    k_scan<<<1, 1024>>>(n);
    k_scatter_ex<<<e_blocks, 256>>>(src, dst, e);

    // layer 0: gather A -> write fp16 mid B
    k_agg<true, false><<<node_blocks, 256>>>(nullptr, n);

    // layer 1: dots from B, refresh weights, gather B -> fp32 out
    k_dots1<<<node_blocks, 256>>>(att + 2 * DD, n);
    k_w1<<<e_blocks, 256>>>(e);
    k_agg<false, true><<<node_blocks, 256>>>((float*)d_out, n);
}

// round 9
// speedup vs baseline: 30.7324x; 1.4518x over previous
#include <cuda_runtime.h>
#include <cuda_fp16.h>
#include <math_constants.h>

#define NN 50000
#define EE 1600000
#define DD 128
#define NEG_SLOPE 0.01f
#define SCAN_B 256
#define NBLK ((NN + SCAN_B - 1) / SCAN_B)   // 196

// Scratch (__device__ globals; no allocation allowed)
__device__ int   g_deg[NN];
__device__ int   g_off[NN + 1];
__device__ int   g_curp[NN];
__device__ int   g_bsum[NBLK];
__device__ int   g_boff[NBLK];
__device__ int2  g_ew[EE];          // (.x = src | dst<<16, .y = exp-weight bits), dst-sorted
__device__ uint2 g_hA[NN * 32];     // fp16x4 per lane: layer-0 gather source
__device__ uint2 g_hB[NN * 32];     // fp16x4 per lane: layer-1 gather source (mid)
__device__ float g_ssrc[NN];
__device__ float g_sdst[NN];

// ---------------- build ---------------------------------------------------------

__global__ void k_zero(int n) {
    int i = blockIdx.x * blockDim.x + threadIdx.x;
    if (i < n) g_deg[i] = 0;
}

__global__ void k_hist(const int* __restrict__ dst, int e) {
    int i = blockIdx.x * blockDim.x + threadIdx.x;
    if (i < e) atomicAdd(&g_deg[dst[i]], 1);
}

// Pass A: per-block exclusive scan of g_deg into g_off; block totals to g_bsum.
__global__ void k_scanA(int n) {
    int i    = blockIdx.x * SCAN_B + threadIdx.x;
    int lane = threadIdx.x & 31;
    int wid  = threadIdx.x >> 5;

    int v = (i < n) ? g_deg[i] : 0;
    int x = v;
    #pragma unroll
    for (int o = 1; o < 32; o <<= 1) {
        int t = __shfl_up_sync(0xffffffffu, x, o);
        if (lane >= o) x += t;
    }
    __shared__ int ws[8];
    if (lane == 31) ws[wid] = x;
    __syncthreads();
    if (wid == 0) {
        int y = (lane < 8) ? ws[lane] : 0;
        #pragma unroll
        for (int o = 1; o < 8; o <<= 1) {
            int t = __shfl_up_sync(0xffffffffu, y, o);
            if (lane >= o) y += t;
        }
        if (lane < 8) ws[lane] = y;
    }
    __syncthreads();
    int pre = (wid > 0) ? ws[wid - 1] : 0;
    int inc = x + pre;
    if (i < n) g_off[i] = inc - v;            // exclusive within block
    if (threadIdx.x == SCAN_B - 1) g_bsum[blockIdx.x] = inc;
}

// Pass B: one block scans NBLK block sums exclusively into g_boff.
__global__ void k_scanB(int nblk) {
    int t    = threadIdx.x;
    int lane = t & 31;
    int wid  = t >> 5;
    int v = (t < nblk) ? g_bsum[t] : 0;
    int x = v;
    #pragma unroll
    for (int o = 1; o < 32; o <<= 1) {
        int u = __shfl_up_sync(0xffffffffu, x, o);
        if (lane >= o) x += u;
    }
    __shared__ int ws[8];
    if (lane == 31) ws[wid] = x;
    __syncthreads();
    if (wid == 0) {
        int y = (lane < 8) ? ws[lane] : 0;
        #pragma unroll
        for (int o = 1; o < 8; o <<= 1) {
            int u = __shfl_up_sync(0xffffffffu, y, o);
            if (lane >= o) y += u;
        }
        if (lane < 8) ws[lane] = y;
    }
    __syncthreads();
    int pre = (wid > 0) ? ws[wid - 1] : 0;
    if (t < nblk) g_boff[t] = x + pre - v;    // exclusive
}

// Pass C: add block prefix; fill g_off/g_curp; g_off[n] = e.
__global__ void k_scanC(int n, int e) {
    int i = blockIdx.x * SCAN_B + threadIdx.x;
    if (i < n) {
        int o = g_off[i] + g_boff[blockIdx.x];
        g_off[i]  = o;
        g_curp[i] = o;
    }
    if (i == 0) g_off[n] = e;
}

// scatter + layer-0 edge weight in one pass (ssrc/sdst already computed by k_prep0).
// No max-subtraction: scores bounded, softmax shift-invariant.
__global__ void k_scatter_ex(const int* __restrict__ src, const int* __restrict__ dst, int e) {
    int i = blockIdx.x * blockDim.x + threadIdx.x;
    if (i >= e) return;
    int s = src[i], d = dst[i];
    float a  = g_ssrc[s] + g_sdst[d];
    float ev = (a > 0.f) ? a : NEG_SLOPE * a;
    float ex = __expf(ev);
    int p = atomicAdd(&g_curp[d], 1);
    g_ew[p] = make_int2((int)((unsigned)s | ((unsigned)d << 16)), __float_as_int(ex));
}

// ---------------- per-layer -----------------------------------------------------

// warp per node: convert external fp32 h into fp16 gather buffer A,
// compute layer-0 attention dots.
__global__ void k_prep0(const float* __restrict__ h_ext, const float* __restrict__ w_row, int n) {
    int gid  = blockIdx.x * blockDim.x + threadIdx.x;
    int node = gid >> 5;
    int lane = threadIdx.x & 31;
    if (node >= n) return;

    float4 v = ((const float4*)h_ext)[node * 32 + lane];
    __half2 p01 = __floats2half2_rn(v.x, v.y);
    __half2 p23 = __floats2half2_rn(v.z, v.w);
    uint2 pk;
    pk.x = *(unsigned int*)&p01;
    pk.y = *(unsigned int*)&p23;
    g_hA[node * 32 + lane] = pk;

    float4 ws = ((const float4*)w_row)[lane];
    float4 wd = ((const float4*)w_row)[32 + lane];
    float ds = v.x * ws.x + v.y * ws.y + v.z * ws.z + v.w * ws.w;
    float dd = v.x * wd.x + v.y * wd.y + v.z * wd.z + v.w * wd.w;
    #pragma unroll
    for (int o = 16; o; o >>= 1) {
        ds += __shfl_xor_sync(0xffffffffu, ds, o);
        dd += __shfl_xor_sync(0xffffffffu, dd, o);
    }
    if (lane == 0) {
        g_ssrc[node] = ds;
        g_sdst[node] = dd;
    }
}

// warp per node: layer-1 attention dots from fp16 mid buffer B.
__global__ void k_dots1(const float* __restrict__ w_row, int n) {
    int gid  = blockIdx.x * blockDim.x + threadIdx.x;
    int node = gid >> 5;
    int lane = threadIdx.x & 31;
    if (node >= n) return;

    uint2 pk = g_hB[node * 32 + lane];
    float2 f01 = __half22float2(*(__half2*)&pk.x);
    float2 f23 = __half22float2(*(__half2*)&pk.y);

    float4 ws = ((const float4*)w_row)[lane];
    float4 wd = ((const float4*)w_row)[32 + lane];
    float ds = f01.x * ws.x + f01.y * ws.y + f23.x * ws.z + f23.y * ws.w;
    float dd = f01.x * wd.x + f01.y * wd.y + f23.x * wd.z + f23.y * wd.w;
    #pragma unroll
    for (int o = 16; o; o >>= 1) {
        ds += __shfl_xor_sync(0xffffffffu, ds, o);
        dd += __shfl_xor_sync(0xffffffffu, dd, o);
    }
    if (lane == 0) {
        g_ssrc[node] = ds;
        g_sdst[node] = dd;
    }
}

// per-edge layer-1 weight refresh (src/dst unpacked from packed word).
__global__ void k_w1(int e) {
    int i = blockIdx.x * blockDim.x + threadIdx.x;
    if (i >= e) return;
    unsigned p = (unsigned)__ldg(&g_ew[i].x);
    int s = (int)(p & 0xFFFFu);
    int d = (int)(p >> 16);
    float a  = g_ssrc[s] + g_sdst[d];
    float ev = (a > 0.f) ? a : NEG_SLOPE * a;
    g_ew[i].y = __float_as_int(__expf(ev));
}

// One warp per node: softmax-weighted aggregation over the node's dst-sorted
// edge run. Loop body: one uniform broadcast LDG.64 (edge record) + one
// coalesced gather LDG.64 + 4 FMA. Register accumulator, normalized direct
// write. No atomics, no RED, no second pass. Buffers selected DEVICE-side
// via template flags (host cannot take the address of __device__ globals).
template <bool SRC_A, bool FP32OUT>
__global__ void k_agg(float* __restrict__ out_f32, int n) {
    int gid  = blockIdx.x * blockDim.x + threadIdx.x;
    int node = gid >> 5;
    int lane = threadIdx.x & 31;
    if (node >= n) return;

    const uint2* __restrict__ hsrc = SRC_A ? g_hA : g_hB;

    int beg = g_off[node];
    int end = g_off[node + 1];

    float4 acc = make_float4(0.f, 0.f, 0.f, 0.f);
    float  sum = 0.f;

    #pragma unroll 4
    for (int k = beg; k < end; k++) {
        int2 q = __ldg(&g_ew[k]);
        int s = (int)((unsigned)q.x & 0xFFFFu);
        float ex = __int_as_float(q.y);
        uint2 pk = __ldg(&hsrc[(size_t)s * 32 + lane]);
        float2 f01 = __half22float2(*(__half2*)&pk.x);
        float2 f23 = __half22float2(*(__half2*)&pk.y);
        acc.x = fmaf(f01.x, ex, acc.x);
        acc.y = fmaf(f01.y, ex, acc.y);
        acc.z = fmaf(f23.x, ex, acc.z);
        acc.w = fmaf(f23.y, ex, acc.w);
        sum  += ex;
    }

    float inv = (sum != 0.f) ? 1.f / sum : 0.f;
    acc.x *= inv; acc.y *= inv; acc.z *= inv; acc.w *= inv;

    if (FP32OUT) {
        ((float4*)out_f32)[node * 32 + lane] = acc;
    } else {
        __half2 p01 = __floats2half2_rn(acc.x, acc.y);
        __half2 p23 = __floats2half2_rn(acc.z, acc.w);
        uint2 pk;
        pk.x = *(unsigned int*)&p01;
        pk.y = *(unsigned int*)&p23;
        g_hB[node * 32 + lane] = pk;
    }
}

// ---------------- launch --------------------------------------------------------

extern "C" void kernel_launch(void* const* d_in, const int* in_sizes, int n_in,
                              void* d_out, int out_size) {
    const float* h   = (const float*)d_in[0];
    const int*   src = (const int*)d_in[1];
    const int*   dst = (const int*)d_in[2];
    const float* att = (const float*)d_in[3];
    int n = in_sizes[0] / DD;
    int e = in_sizes[1];

    int node_blocks = (n * 32 + 255) / 256;
    int n_blocks    = (n + SCAN_B - 1) / SCAN_B;
    int e_blocks    = (e + 255) / 256;

    // layer-0 scalars + fp16 buffer (independent of build)
    k_prep0<<<node_blocks, 256>>>(h, att, n);

    // build dst-sorted packed edge list, with layer-0 weights fused in
    k_zero<<<n_blocks, SCAN_B>>>(n);
    k_hist<<<e_blocks, 256>>>(dst, e);
    k_scanA<<<n_blocks, SCAN_B>>>(n);
    k_scanB<<<1, SCAN_B>>>(n_blocks);
    k_scanC<<<n_blocks, SCAN_B>>>(n, e);
    k_scatter_ex<<<e_blocks, 256>>>(src, dst, e);

    // layer 0: gather A -> write fp16 mid B
    k_agg<true, false><<<node_blocks, 256>>>(nullptr, n);

    // layer 1: dots from B, refresh weights, gather B -> fp32 out
    k_dots1<<<node_blocks, 256>>>(att + 2 * DD, n);
    k_w1<<<e_blocks, 256>>>(e);
    k_agg<false, true><<<node_blocks, 256>>>((float*)d_out, n);
}